// round 1
// baseline (speedup 1.0000x reference)
#include <cuda_runtime.h>
#include <cstddef>

// ErbNorm: per-(b,f) EMA normalization scan over T.
//   mu_t  = a*mu_{t-1} + (1-a)*x_t
//   var_t = a*var_{t-1} + (1-a)*(x_t - mu_t)^2
//   out_t = (x_t - mu_t) / (sqrt(var_t) + eps)
//
// Layout x[b][t][f], F=64: one thread per (b,f) lane. Lanes with consecutive f
// give fully coalesced 128B/warp per timestep. Loop-carried deps are two FFMAs
// (mu, var), so throughput is fine; the hazard is DRAM latency with only
// ~3.5 warps/SM. We software-pipeline: two 16-wide register blocks,
// prefetch distance = 2 blocks (~32 iterations in flight).

#ifndef ERB_T
#define ERB_T 4000
#endif
#define ERB_F 64
#define ERB_U 16   // block (unroll) size; T must be divisible by 2*U

__global__ void __launch_bounds__(32, 16)
erbnorm_kernel(const float* __restrict__ x, float* __restrict__ out, int T)
{
    // 32-thread blocks: blockIdx encodes (b, f-half) for finer load balance.
    const int b     = blockIdx.x >> 1;
    const int f     = ((blockIdx.x & 1) << 5) + threadIdx.x;

    const float alpha = 0.99f;
    const float beta  = (float)(1.0 - 0.99);              // match jnp (1.0 - ALPHA)
    const float step  = (float)((-90.0 - (-60.0)) / 63.0); // (INIT_LO-INIT_HI)/(F-1)

    float mu  = -60.0f + (float)f * step;
    float var = 1600.0f;                                   // 40^2

    const size_t base = (size_t)b * (size_t)T * ERB_F + (size_t)f;
    const float* __restrict__ p = x   + base;   // prefetch pointer (advanced)
    float*       __restrict__ q = out + base;   // store pointer

    float c0[ERB_U], c1[ERB_U];

    // Prologue: load blocks 0 and 1.
    #pragma unroll
    for (int i = 0; i < ERB_U; ++i) c0[i] = p[i * ERB_F];
    #pragma unroll
    for (int i = 0; i < ERB_U; ++i) c1[i] = p[(ERB_U + i) * ERB_F];
    p += 2 * ERB_U * ERB_F;   // p now points at block 2

    const int NB = T / ERB_U;   // 250 blocks, even

    for (int blk = 0; blk < NB; blk += 2) {
        const bool more = (blk + 2) < NB;

        // ---- process block blk (c0), prefetch block blk+2 into c0 ----
        #pragma unroll
        for (int i = 0; i < ERB_U; ++i) {
            float xt = c0[i];
            if (more) c0[i] = p[i * ERB_F];           // prefetch (WAR after read)
            mu = fmaf(alpha, mu, beta * xt);
            float d = xt - mu;
            var = fmaf(alpha, var, (beta * d) * d);
            q[i * ERB_F] = d * rsqrtf(var);
        }
        q += ERB_U * ERB_F;

        // ---- process block blk+1 (c1), prefetch block blk+3 into c1 ----
        #pragma unroll
        for (int i = 0; i < ERB_U; ++i) {
            float xt = c1[i];
            if (more) c1[i] = p[(ERB_U + i) * ERB_F];
            mu = fmaf(alpha, mu, beta * xt);
            float d = xt - mu;
            var = fmaf(alpha, var, (beta * d) * d);
            q[i * ERB_F] = d * rsqrtf(var);
        }
        q += ERB_U * ERB_F;
        p += 2 * ERB_U * ERB_F;
    }
}

extern "C" void kernel_launch(void* const* d_in, const int* in_sizes, int n_in,
                              void* d_out, int out_size)
{
    const float* x = (const float*)d_in[0];
    float* out = (float*)d_out;

    const int T = ERB_T;                       // 4000
    const int B = in_sizes[0] / (T * ERB_F);   // 256

    dim3 grid(B * 2);   // 512 blocks of 32 threads -> one warp per block
    dim3 block(32);
    erbnorm_kernel<<<grid, block>>>(x, out, T);
}

// round 2
// speedup vs baseline: 1.8130x; 1.8130x over previous
#include <cuda_runtime.h>
#include <cstddef>
#include <cstdint>

// ErbNorm: per-(b,f) EMA normalization scan over T.
//   mu_t  = a*mu_{t-1} + (1-a)*x_t
//   var_t = a*var_{t-1} + (1-a)*(x_t - mu_t)^2
//   out_t = (x_t - mu_t) / (sqrt(var_t) + eps)
//
// One warp per (b, f-half) lane group; the scan itself is sequential per lane.
// The latency fix vs round 1: a deep cp.async smem ring (256 stages x 128B =
// 32KB, 8 commit groups of 32 steps) keeps ~28KB of loads in flight per warp
// (vs ~7KB register cap), 4x the per-SM bandwidth-delay product at 3.5
// warps/SM. Loads use cooperative 16B cp.async.cg (8 threads per 128B stage).

#ifndef ERB_T
#define ERB_T 4000
#endif
#define ERB_F   64
#define ERB_G   32            // timesteps per commit group
#define ERB_NGR 8             // groups in ring
#define ERB_NST (ERB_G * ERB_NGR)   // 256 stages (32KB smem)

__device__ __forceinline__ void cp_async16(uint32_t saddr, const void* gaddr) {
    asm volatile("cp.async.cg.shared.global [%0], [%1], 16;\n"
                 :: "r"(saddr), "l"(gaddr));
}
__device__ __forceinline__ void cp_commit() {
    asm volatile("cp.async.commit_group;\n");
}
__device__ __forceinline__ void cp_wait7() {
    asm volatile("cp.async.wait_group 7;\n");
}

__global__ void __launch_bounds__(32)
erbnorm_kernel(const float* __restrict__ x, float* __restrict__ out, int T)
{
    __shared__ float buf[ERB_NST * 32];   // [stage][lane], 128B per stage

    const int tid  = threadIdx.x;
    const int b    = blockIdx.x >> 1;
    const int half = blockIdx.x & 1;
    const int f    = (half << 5) + tid;

    const float alpha = 0.99f;
    const float beta  = (float)(1.0 - 0.99);
    const float step  = (float)((-90.0 - (-60.0)) / 63.0);

    float mu  = fmaf((float)f, step, -60.0f);
    float var = 1600.0f;

    // Base of this block's 32-lane half for timestep 0.
    const size_t half_base = (size_t)b * (size_t)T * ERB_F + (size_t)(half << 5);

    // Cooperative load mapping: thread = (row r_off = tid>>3, chunk c = tid&7).
    const int r_off = tid >> 3;     // stage offset within a 4-stage round
    const int c_off = (tid & 7) * 4; // float offset of this thread's 16B chunk

    // gmem pointer for this thread's chunk at timestep (t0 + r_off):
    const float* gsrc = x + half_base + (size_t)r_off * ERB_F + c_off;
    // smem byte address of this thread's chunk in stage r_off:
    const uint32_t sbase =
        (uint32_t)__cvta_generic_to_shared(buf) + (uint32_t)(r_off * 128 + c_off * 4);

    // ---- prologue: fill all 8 groups (timesteps 0..255) ----
    {
        const float* p = gsrc;
        uint32_t sa = sbase;
        #pragma unroll
        for (int grp = 0; grp < ERB_NGR; ++grp) {
            #pragma unroll
            for (int r = 0; r < 8; ++r) {
                cp_async16(sa + (uint32_t)(r * 4 * 128), p + (size_t)(r * 4) * ERB_F);
            }
            cp_commit();
            sa += ERB_G * 128;
            p  += (size_t)ERB_G * ERB_F;
        }
    }

    float* q = out + half_base + tid;             // this lane's output stream
    const float* sp = &buf[tid];                  // this lane's smem read stream
    const float* pref = gsrc + (size_t)ERB_NST * ERB_F;  // next timestep to fetch

    const int TOTAL_G = T / ERB_G;                // 125
    int ring = 0;

    for (int g = 0; g < TOTAL_G; ++g) {
        cp_wait7();          // oldest of the 8 pending groups retired
        __syncwarp();

        // Pull the whole group into registers first (batched LDS, max MLP).
        float xt[ERB_G];
        const float* s0 = sp + ring * (ERB_G * 32);
        #pragma unroll
        for (int i = 0; i < ERB_G; ++i) xt[i] = s0[i * 32];

        // Refill this slot with group g+8 (issue early, fire-and-forget).
        if (g + ERB_NGR < TOTAL_G) {
            uint32_t sa = sbase + (uint32_t)(ring * ERB_G * 128);
            #pragma unroll
            for (int r = 0; r < 8; ++r) {
                cp_async16(sa + (uint32_t)(r * 4 * 128), pref + (size_t)(r * 4) * ERB_F);
            }
            pref += (size_t)ERB_G * ERB_F;
        }
        cp_commit();         // always commit (empty groups keep the count exact)

        // Sequential scan over the 32 buffered timesteps.
        #pragma unroll
        for (int i = 0; i < ERB_G; ++i) {
            mu = fmaf(alpha, mu, beta * xt[i]);
            float d = xt[i] - mu;
            var = fmaf(alpha, var, (beta * d) * d);
            q[i * ERB_F] = d * rsqrtf(var);
        }
        q += ERB_G * ERB_F;

        ring = (ring + 1 == ERB_NGR) ? 0 : ring + 1;
    }
}

extern "C" void kernel_launch(void* const* d_in, const int* in_sizes, int n_in,
                              void* d_out, int out_size)
{
    const float* x = (const float*)d_in[0];
    float* out = (float*)d_out;

    const int T = ERB_T;                       // 4000
    const int B = in_sizes[0] / (T * ERB_F);   // 256

    dim3 grid(B * 2);   // 512 single-warp blocks
    dim3 block(32);
    erbnorm_kernel<<<grid, block>>>(x, out, T);
}

// round 3
// speedup vs baseline: 1.9754x; 1.0896x over previous
#include <cuda_runtime.h>
#include <cstddef>
#include <cstdint>

// ErbNorm: per-(b,f) EMA normalization scan over T.
//   mu_t  = a*mu_{t-1} + (1-a)*x_t
//   var_t = a*var_{t-1} + (1-a)*(x_t - mu_t)^2
//   out_t = (x_t - mu_t) / (sqrt(var_t) + eps)
//
// One warp per (b, f-half). Round-3 structure: cp.async smem ring (8 slots x
// 16 steps x 128B = 16KB) PLUS a register double-buffer. Per group iteration:
//   1. refill the slot freed last iteration (issue-first, fire-and-forget)
//   2. wait_group 7 -> LDS next group into the alternate register set
//   3. scan the current group from registers (covers wait wakeup + LDS lat)
// Even/odd unrolled loop avoids register-buffer swap MOVs.

#ifndef ERB_T
#define ERB_T 4000
#endif
#define ERB_F   64
#define ERB_G   16                  // timesteps per commit group
#define ERB_NGR 8                   // ring slots
#define ERB_SLOT_FLOATS (ERB_G * 32)    // 512 floats per slot
#define ERB_SLOT_BYTES  (ERB_G * 128)   // 2048 bytes per slot

__device__ __forceinline__ void cp_async16(uint32_t saddr, const void* gaddr) {
    asm volatile("cp.async.cg.shared.global [%0], [%1], 16;\n"
                 :: "r"(saddr), "l"(gaddr));
}
__device__ __forceinline__ void cp_commit() {
    asm volatile("cp.async.commit_group;\n");
}
__device__ __forceinline__ void cp_wait7() {
    asm volatile("cp.async.wait_group 7;\n");
}

__global__ void __launch_bounds__(32)
erbnorm_kernel(const float* __restrict__ x, float* __restrict__ out, int T)
{
    __shared__ float buf[ERB_NGR * ERB_SLOT_FLOATS];   // 16KB

    const int tid  = threadIdx.x;
    const int b    = blockIdx.x >> 1;
    const int half = blockIdx.x & 1;
    const int f    = (half << 5) + tid;

    const float alpha = 0.99f;
    const float beta  = (float)(1.0 - 0.99);
    const float step  = (float)((-90.0 - (-60.0)) / 63.0);

    float mu  = fmaf((float)f, step, -60.0f);
    float var = 1600.0f;

    const size_t half_base = (size_t)b * (size_t)T * ERB_F + (size_t)(half << 5);

    // Cooperative load mapping: 8 threads cover one 128B stage (4 rows/thread).
    const int r_off = tid >> 3;          // row within a 4-row round
    const int c_off = (tid & 7) * 4;     // float offset of this thread's 16B chunk

    const float* gsrc = x + half_base + (size_t)r_off * ERB_F + c_off;
    const uint32_t sbase =
        (uint32_t)__cvta_generic_to_shared(buf) + (uint32_t)(r_off * 128 + c_off * 4);

    // ---- prologue: fill all 8 slots (groups 0..7) ----
    {
        const float* p = gsrc;
        uint32_t sa = sbase;
        #pragma unroll
        for (int grp = 0; grp < ERB_NGR; ++grp) {
            #pragma unroll
            for (int r = 0; r < 4; ++r)
                cp_async16(sa + (uint32_t)(r * 4 * 128), p + (size_t)(r * 4) * ERB_F);
            cp_commit();
            sa += ERB_SLOT_BYTES;
            p  += (size_t)ERB_G * ERB_F;
        }
    }

    const int NG = T / ERB_G;                 // 250 (even)
    const float* sp   = &buf[tid];            // this lane's smem column
    float*       q    = out + half_base + tid;
    const float* pref = gsrc + (size_t)ERB_NGR * ERB_G * ERB_F;  // group 8

    float A[ERB_G], Bv[ERB_G];

    // Load group 0 into A.
    cp_wait7();
    __syncwarp();
    #pragma unroll
    for (int i = 0; i < ERB_G; ++i) A[i] = sp[i * 32];

    // Iteration body as a macro so even/odd phases share code but alternate
    // register buffers without copy MOVs.
#define ERB_BODY(CUR, NXT, g)                                                  \
    {                                                                          \
        /* 1. refill slot (g & 7) with group (g + 8) */                        \
        if ((g) + ERB_NGR < NG) {                                              \
            uint32_t sa = sbase + (uint32_t)(((g) & 7) * ERB_SLOT_BYTES);      \
            _Pragma("unroll")                                                  \
            for (int r = 0; r < 4; ++r)                                        \
                cp_async16(sa + (uint32_t)(r * 4 * 128),                       \
                           pref + (size_t)(r * 4) * ERB_F);                    \
            pref += (size_t)ERB_G * ERB_F;                                     \
        }                                                                      \
        cp_commit();                                                           \
        /* 2. wait for group g+1, pull it into NXT */                          \
        cp_wait7();                                                            \
        __syncwarp();                                                          \
        {                                                                      \
            const float* sn = sp + (((g) + 1) & 7) * ERB_SLOT_FLOATS;          \
            _Pragma("unroll")                                                  \
            for (int i = 0; i < ERB_G; ++i) NXT[i] = sn[i * 32];               \
        }                                                                      \
        /* 3. scan group g from CUR */                                         \
        _Pragma("unroll")                                                      \
        for (int i = 0; i < ERB_G; ++i) {                                      \
            mu = fmaf(alpha, mu, beta * CUR[i]);                               \
            float d = CUR[i] - mu;                                             \
            var = fmaf(alpha, var, (beta * d) * d);                            \
            __stcs(q + i * ERB_F, d * rsqrtf(var));                            \
        }                                                                      \
        q += ERB_G * ERB_F;                                                    \
    }

    for (int g = 0; g < NG; g += 2) {
        ERB_BODY(A, Bv, g)
        ERB_BODY(Bv, A, g + 1)
    }
#undef ERB_BODY
}

extern "C" void kernel_launch(void* const* d_in, const int* in_sizes, int n_in,
                              void* d_out, int out_size)
{
    const float* x = (const float*)d_in[0];
    float* out = (float*)d_out;

    const int T = ERB_T;                       // 4000
    const int B = in_sizes[0] / (T * ERB_F);   // 256

    dim3 grid(B * 2);   // 512 single-warp blocks
    dim3 block(32);
    erbnorm_kernel<<<grid, block>>>(x, out, T);
}